// round 1
// baseline (speedup 1.0000x reference)
#include <cuda_runtime.h>
#include <math_constants.h>

#define N_NODES  100000
#define N_EDGES  1600000
#define D        64
#define N_GRAPHS 64

// Scratch (allocation-free rule: device globals)
__device__ float4 g_agg[N_NODES * (D / 4)];   // 25.6 MB accumulator
__device__ float  g_deg[N_NODES];
__device__ float  g_h[N_NODES * D];           // layer-0 activations

// sm_90+ vector reduction (no return) — 1 instruction per 16 bytes
__device__ __forceinline__ void red_add_v4(float4* addr, float4 v) {
    asm volatile("red.global.add.v4.f32 [%0], {%1, %2, %3, %4};"
                 :: "l"(addr), "f"(v.x), "f"(v.y), "f"(v.z), "f"(v.w)
                 : "memory");
}

// float atomic max via signed-max (>=0) / unsigned-min (<0); init must be -inf
__device__ __forceinline__ void atomicMaxFloat(float* addr, float val) {
    if (val >= 0.0f) atomicMax((int*)addr, __float_as_int(val));
    else             atomicMin((unsigned int*)addr, __float_as_uint(val));
}

// ---------------------------------------------------------------------------
// Init: zero agg + deg, set pooled output f to -inf
// ---------------------------------------------------------------------------
__global__ void k_init(float* __restrict__ f_out) {
    const int NAGG = N_NODES * (D / 4);
    int idx = blockIdx.x * blockDim.x + threadIdx.x;
    if (idx < NAGG) {
        g_agg[idx] = make_float4(0.f, 0.f, 0.f, 0.f);
    } else if (idx < NAGG + N_NODES) {
        g_deg[idx - NAGG] = 0.0f;
    } else if (idx < NAGG + N_NODES + N_GRAPHS * D) {
        f_out[idx - NAGG - N_NODES] = -CUDART_INF_F;
    }
}

// ---------------------------------------------------------------------------
// Edge scatter: 16 threads per edge, one float4 vector-reduction each.
// ---------------------------------------------------------------------------
template <bool COUNT_DEG>
__global__ void k_edge(const float* __restrict__ feat,
                       const int* __restrict__ src,
                       const int* __restrict__ dst) {
    int idx = blockIdx.x * blockDim.x + threadIdx.x;   // 25.6M work items
    if (idx >= N_EDGES * 16) return;
    int e = idx >> 4;
    int q = idx & 15;
    int s = __ldg(&src[e]);
    int d = __ldg(&dst[e]);
    float4 v = __ldg(reinterpret_cast<const float4*>(feat) + s * (D / 4) + q);
    red_add_v4(&g_agg[d * (D / 4) + q], v);
    if (COUNT_DEG && q == 0) atomicAdd(&g_deg[d], 1.0f);
}

// ---------------------------------------------------------------------------
// Node transform: out = act( in @ Wself + (agg/deg) @ Wneigh )
// One warp per node; W matrices staged in smem; input row broadcast via shfl.
// Optionally zeroes agg after reading (so the next edge pass can accumulate),
// and optionally fuses the per-graph max-pool.
// ---------------------------------------------------------------------------
template <bool RELU, bool ZERO_AGG, bool POOL>
__global__ void __launch_bounds__(256)
k_node(const float* __restrict__ in,
       const float* __restrict__ Wself,
       const float* __restrict__ Wneigh,
       float* __restrict__ out,
       const int* __restrict__ graph_ids,
       float* __restrict__ fpool) {
    __shared__ float sWs[D * D];
    __shared__ float sWn[D * D];
    for (int i = threadIdx.x; i < D * D; i += blockDim.x) {
        sWs[i] = Wself[i];
        sWn[i] = Wneigh[i];
    }
    __syncthreads();

    int lane = threadIdx.x & 31;
    int warp = threadIdx.x >> 5;
    int node = blockIdx.x * (blockDim.x >> 5) + warp;
    if (node >= N_NODES) return;

    const float* xrow = in + node * D;
    float* aggf = reinterpret_cast<float*>(g_agg) + node * D;

    float x0 = xrow[lane];
    float x1 = xrow[lane + 32];
    float inv = 1.0f / fmaxf(g_deg[node], 1.0f);
    float a0 = aggf[lane] * inv;
    float a1 = aggf[lane + 32] * inv;
    if (ZERO_AGG) { aggf[lane] = 0.0f; aggf[lane + 32] = 0.0f; }

    float acc0 = 0.f, acc1 = 0.f;
#pragma unroll
    for (int k = 0; k < 32; k++) {
        float bx = __shfl_sync(0xffffffffu, x0, k);
        float ba = __shfl_sync(0xffffffffu, a0, k);
        acc0 += bx * sWs[k * D + lane]      + ba * sWn[k * D + lane];
        acc1 += bx * sWs[k * D + 32 + lane] + ba * sWn[k * D + 32 + lane];
    }
#pragma unroll
    for (int k = 0; k < 32; k++) {
        float bx = __shfl_sync(0xffffffffu, x1, k);
        float ba = __shfl_sync(0xffffffffu, a1, k);
        int r = k + 32;
        acc0 += bx * sWs[r * D + lane]      + ba * sWn[r * D + lane];
        acc1 += bx * sWs[r * D + 32 + lane] + ba * sWn[r * D + 32 + lane];
    }

    if (RELU) { acc0 = fmaxf(acc0, 0.f); acc1 = fmaxf(acc1, 0.f); }

    out[node * D + lane]      = acc0;
    out[node * D + lane + 32] = acc1;

    if (POOL) {
        int g = __ldg(&graph_ids[node]);
        atomicMaxFloat(&fpool[g * D + lane],      acc0);
        atomicMaxFloat(&fpool[g * D + 32 + lane], acc1);
    }
}

// ---------------------------------------------------------------------------
extern "C" void kernel_launch(void* const* d_in, const int* in_sizes, int n_in,
                              void* d_out, int out_size) {
    const float* x   = (const float*)d_in[0];
    const int*   src = (const int*)  d_in[1];
    const int*   dst = (const int*)  d_in[2];
    const int*   gid = (const int*)  d_in[3];
    const float* W0s = (const float*)d_in[4];
    const float* W0n = (const float*)d_in[5];
    const float* W1s = (const float*)d_in[6];
    const float* W1n = (const float*)d_in[7];

    float* out = (float*)d_out;
    float* f   = out;                   // [64, 64] pooled output
    float* e   = out + N_GRAPHS * D;    // [100000, 64] node output

    void* hptr = nullptr;
    cudaGetSymbolAddress(&hptr, g_h);
    float* h = (float*)hptr;

    const int init_n = N_NODES * (D / 4) + N_NODES + N_GRAPHS * D;
    k_init<<<(init_n + 255) / 256, 256>>>(f);

    // Layer 0
    k_edge<true><<<(N_EDGES * 16) / 256, 256>>>(x, src, dst);
    k_node<true, true, false><<<(N_NODES + 7) / 8, 256>>>(x, W0s, W0n, h, gid, f);

    // Layer 1 (+ fused graph max-pool)
    k_edge<false><<<(N_EDGES * 16) / 256, 256>>>(h, src, dst);
    k_node<false, false, true><<<(N_NODES + 7) / 8, 256>>>(h, W1s, W1n, e, gid, f);
}

// round 2
// speedup vs baseline: 1.3757x; 1.3757x over previous
#include <cuda_runtime.h>
#include <math_constants.h>

#define N_NODES  100000
#define N_EDGES  1600000
#define D        64
#define N_GRAPHS 64

// ---------------- device scratch (no allocations allowed) ------------------
__device__ float g_agg[N_NODES * D];      // neighbor sums (overwritten each layer)
__device__ float g_deg[N_NODES];
__device__ float g_h[N_NODES * D];        // layer-0 activations
__device__ int   g_cnt[N_NODES];          // histogram
__device__ int   g_off[N_NODES + 1];      // CSR offsets
__device__ int   g_cur[N_NODES];          // scatter cursors
__device__ int   g_esrc[N_EDGES];         // src ids grouped by dst

// float atomic max via signed-max (>=0) / unsigned-min (<0); init must be -inf
__device__ __forceinline__ void atomicMaxFloat(float* addr, float val) {
    if (val >= 0.0f) atomicMax((int*)addr, __float_as_int(val));
    else             atomicMin((unsigned int*)addr, __float_as_uint(val));
}

// ---------------------------------------------------------------------------
// init: zero histogram, set pooled output f to -inf
// ---------------------------------------------------------------------------
__global__ void k_init(float* __restrict__ f_out) {
    int idx = blockIdx.x * blockDim.x + threadIdx.x;
    if (idx < N_NODES) g_cnt[idx] = 0;
    else if (idx < N_NODES + N_GRAPHS * D) f_out[idx - N_NODES] = -CUDART_INF_F;
}

// histogram of dst
__global__ void k_hist(const int* __restrict__ dst) {
    int e = blockIdx.x * blockDim.x + threadIdx.x;
    if (e < N_EDGES) atomicAdd(&g_cnt[dst[e]], 1);
}

// single-block exclusive scan over 100k counts -> offsets, cursors, degrees
__global__ void __launch_bounds__(1024) k_scan() {
    __shared__ int ssum[1024];
    const int CH = (N_NODES + 1023) / 1024;       // 98
    int t = threadIdx.x;
    int begin = t * CH;
    int endc = min(begin + CH, N_NODES);
    int s = 0;
    for (int i = begin; i < endc; i++) s += g_cnt[i];
    ssum[t] = s;
    __syncthreads();
    for (int o = 1; o < 1024; o <<= 1) {
        int v = (t >= o) ? ssum[t - o] : 0;
        __syncthreads();
        ssum[t] += v;
        __syncthreads();
    }
    int run = ssum[t] - s;                        // exclusive prefix
    for (int i = begin; i < endc; i++) {
        int c = g_cnt[i];
        g_off[i] = run;
        g_cur[i] = run;
        g_deg[i] = (float)c;
        run += c;
    }
    if (endc == N_NODES && begin < N_NODES) g_off[N_NODES] = run;
}

// scatter src ids into dst-grouped order
__global__ void k_scatter(const int* __restrict__ src, const int* __restrict__ dst) {
    int e = blockIdx.x * blockDim.x + threadIdx.x;
    if (e >= N_EDGES) return;
    int p = atomicAdd(&g_cur[dst[e]], 1);
    g_esrc[p] = src[e];
}

// ---------------------------------------------------------------------------
// CSR aggregation: one warp per dst node, register accumulation, single store.
// ---------------------------------------------------------------------------
__global__ void __launch_bounds__(256) k_agg(const float* __restrict__ feat) {
    int lane = threadIdx.x & 31;
    int node = (blockIdx.x * blockDim.x + threadIdx.x) >> 5;
    if (node >= N_NODES) return;
    int start = g_off[node];
    int end   = g_off[node + 1];
    float a0 = 0.f, a1 = 0.f;
    for (int base = start; base < end; base += 32) {
        int m = min(end - base, 32);
        int sl = g_esrc[base + ((lane < m) ? lane : 0)];
        int j = 0;
        for (; j + 8 <= m; j += 8) {
            int ss[8];
#pragma unroll
            for (int u = 0; u < 8; u++) ss[u] = __shfl_sync(0xffffffffu, sl, j + u);
            float t0[8], t1[8];
#pragma unroll
            for (int u = 0; u < 8; u++) {
                t0[u] = __ldg(&feat[ss[u] * D + lane]);
                t1[u] = __ldg(&feat[ss[u] * D + 32 + lane]);
            }
#pragma unroll
            for (int u = 0; u < 8; u++) { a0 += t0[u]; a1 += t1[u]; }
        }
        for (; j < m; j++) {
            int sj = __shfl_sync(0xffffffffu, sl, j);
            a0 += __ldg(&feat[sj * D + lane]);
            a1 += __ldg(&feat[sj * D + 32 + lane]);
        }
    }
    g_agg[node * D + lane]      = a0;
    g_agg[node * D + 32 + lane] = a1;
}

// ---------------------------------------------------------------------------
// Node transform as block-tiled GEMM:
//   out[128-node tile][64] = [x | agg/deg] (128x128)  @  [Wself; Wneigh] (128x64)
// 256 threads, each computes 8 nodes x 4 cols.
// ---------------------------------------------------------------------------
#define TN 128
#define PITCH 132   // k-major input tile pitch (floats), 16B-aligned rows

template <bool RELU, bool POOL>
__global__ void __launch_bounds__(256)
k_gemm(const float* __restrict__ in,
       const float* __restrict__ Wself,
       const float* __restrict__ Wneigh,
       float* __restrict__ out,
       const int* __restrict__ graph_ids,
       float* __restrict__ fpool) {
    extern __shared__ float smem[];
    float* sIn = smem;                 // [128 k][PITCH] node-major rows
    float* sW  = smem + 128 * PITCH;   // [128 k][64 cols]

    int tid   = threadIdx.x;
    int node0 = blockIdx.x * TN;

    // load W tile: rows 0-63 = Wself, 64-127 = Wneigh (float4 per thread-iter)
    for (int idx = tid; idx < 128 * 16; idx += 256) {
        int k  = idx >> 4;
        int c4 = (idx & 15) << 2;
        const float* wsrc = (k < 64) ? &Wself[k * D + c4] : &Wneigh[(k - 64) * D + c4];
        *(float4*)&sW[k * D + c4] = *(const float4*)wsrc;
    }

    // load input tile transposed: sIn[k][n] ; k<64 from x, k>=64 from agg/deg
    for (int idx = tid; idx < TN * 32; idx += 256) {
        int n = idx >> 5;          // local node
        int c = idx & 31;          // float4 chunk: 0-15 => x, 16-31 => agg
        int node = node0 + n;
        int k = c << 2;            // both halves land at k = 4c
        float4 v = make_float4(0.f, 0.f, 0.f, 0.f);
        if (node < N_NODES) {
            if (c < 16) {
                v = *(const float4*)&in[node * D + k];
            } else {
                v = *(const float4*)&g_agg[node * D + (k - 64)];
                float inv = 1.0f / fmaxf(g_deg[node], 1.0f);
                v.x *= inv; v.y *= inv; v.z *= inv; v.w *= inv;
            }
        }
        sIn[(k + 0) * PITCH + n] = v.x;
        sIn[(k + 1) * PITCH + n] = v.y;
        sIn[(k + 2) * PITCH + n] = v.z;
        sIn[(k + 3) * PITCH + n] = v.w;
    }
    __syncthreads();

    int cx = tid & 15;     // col group: cols 4*cx .. 4*cx+3
    int nx = tid >> 4;     // node group: nodes 8*nx .. 8*nx+7

    float acc[8][4];
#pragma unroll
    for (int i = 0; i < 8; i++)
#pragma unroll
        for (int j = 0; j < 4; j++) acc[i][j] = 0.f;

#pragma unroll 4
    for (int k = 0; k < 128; k++) {
        float4 w  = *(float4*)&sW[k * D + 4 * cx];
        float4 p0 = *(float4*)&sIn[k * PITCH + 8 * nx];
        float4 p1 = *(float4*)&sIn[k * PITCH + 8 * nx + 4];
        float p[8] = {p0.x, p0.y, p0.z, p0.w, p1.x, p1.y, p1.z, p1.w};
#pragma unroll
        for (int i = 0; i < 8; i++) {
            acc[i][0] += p[i] * w.x;
            acc[i][1] += p[i] * w.y;
            acc[i][2] += p[i] * w.z;
            acc[i][3] += p[i] * w.w;
        }
    }

    // store + optional relu + optional fused per-graph max pool
    float4 runmax = make_float4(-CUDART_INF_F, -CUDART_INF_F, -CUDART_INF_F, -CUDART_INF_F);
    int curg = -1;
#pragma unroll
    for (int i = 0; i < 8; i++) {
        int node = node0 + 8 * nx + i;
        if (node >= N_NODES) break;
        float4 o = make_float4(acc[i][0], acc[i][1], acc[i][2], acc[i][3]);
        if (RELU) {
            o.x = fmaxf(o.x, 0.f); o.y = fmaxf(o.y, 0.f);
            o.z = fmaxf(o.z, 0.f); o.w = fmaxf(o.w, 0.f);
        }
        *(float4*)&out[node * D + 4 * cx] = o;
        if (POOL) {
            int g = __ldg(&graph_ids[node]);
            if (g != curg) {
                if (curg >= 0) {
                    atomicMaxFloat(&fpool[curg * D + 4 * cx + 0], runmax.x);
                    atomicMaxFloat(&fpool[curg * D + 4 * cx + 1], runmax.y);
                    atomicMaxFloat(&fpool[curg * D + 4 * cx + 2], runmax.z);
                    atomicMaxFloat(&fpool[curg * D + 4 * cx + 3], runmax.w);
                }
                curg = g;
                runmax = make_float4(-CUDART_INF_F, -CUDART_INF_F, -CUDART_INF_F, -CUDART_INF_F);
            }
            runmax.x = fmaxf(runmax.x, o.x);
            runmax.y = fmaxf(runmax.y, o.y);
            runmax.z = fmaxf(runmax.z, o.z);
            runmax.w = fmaxf(runmax.w, o.w);
        }
    }
    if (POOL && curg >= 0) {
        atomicMaxFloat(&fpool[curg * D + 4 * cx + 0], runmax.x);
        atomicMaxFloat(&fpool[curg * D + 4 * cx + 1], runmax.y);
        atomicMaxFloat(&fpool[curg * D + 4 * cx + 2], runmax.z);
        atomicMaxFloat(&fpool[curg * D + 4 * cx + 3], runmax.w);
    }
}

// ---------------------------------------------------------------------------
extern "C" void kernel_launch(void* const* d_in, const int* in_sizes, int n_in,
                              void* d_out, int out_size) {
    const float* x   = (const float*)d_in[0];
    const int*   src = (const int*)  d_in[1];
    const int*   dst = (const int*)  d_in[2];
    const int*   gid = (const int*)  d_in[3];
    const float* W0s = (const float*)d_in[4];
    const float* W0n = (const float*)d_in[5];
    const float* W1s = (const float*)d_in[6];
    const float* W1n = (const float*)d_in[7];

    float* out = (float*)d_out;
    float* f   = out;                   // [64, 64] pooled
    float* e   = out + N_GRAPHS * D;    // [100000, 64]

    void* hptr = nullptr;
    cudaGetSymbolAddress(&hptr, g_h);
    float* h = (float*)hptr;

    static bool attr_done = false;
    const int gemm_smem = (128 * PITCH + 128 * D) * (int)sizeof(float);
    if (!attr_done) {
        cudaFuncSetAttribute(k_gemm<true, false>,
                             cudaFuncAttributeMaxDynamicSharedMemorySize, gemm_smem);
        cudaFuncSetAttribute(k_gemm<false, true>,
                             cudaFuncAttributeMaxDynamicSharedMemorySize, gemm_smem);
        attr_done = true;
    }

    const int EB = (N_EDGES + 255) / 256;

    k_init<<<(N_NODES + N_GRAPHS * D + 255) / 256, 256>>>(f);
    k_hist<<<EB, 256>>>(dst);
    k_scan<<<1, 1024>>>();
    k_scatter<<<EB, 256>>>(src, dst);

    const int AGG_B = (N_NODES * 32 + 255) / 256;
    const int GEMM_B = (N_NODES + TN - 1) / TN;

    // Layer 0
    k_agg<<<AGG_B, 256>>>(x);
    k_gemm<true, false><<<GEMM_B, 256, gemm_smem>>>(x, W0s, W0n, h, gid, f);

    // Layer 1 + fused pool
    k_agg<<<AGG_B, 256>>>(h);
    k_gemm<false, true><<<GEMM_B, 256, gemm_smem>>>(h, W1s, W1n, e, gid, f);
}

// round 3
// speedup vs baseline: 2.4569x; 1.7859x over previous
#include <cuda_runtime.h>
#include <math_constants.h>

#define N_NODES  100000
#define N_EDGES  1600000
#define D        64
#define N_GRAPHS 64
#define NBLK     ((N_NODES + 1023) / 1024)   // 98 scan blocks

// ---------------- device scratch (no allocations allowed) ------------------
__device__ float g_agg[N_NODES * D];      // neighbor sums (overwritten each layer)
__device__ float g_deg[N_NODES];
__device__ float g_h[N_NODES * D];        // layer-0 activations
__device__ int   g_cnt[N_NODES];          // histogram
__device__ int   g_off[N_NODES + 1];      // CSR offsets
__device__ int   g_cur[N_NODES];          // scatter cursors
__device__ int   g_esrc[N_EDGES];         // src ids grouped by dst
__device__ int   g_bsum[NBLK];            // per-block scan sums
__device__ int   g_bbase[NBLK];           // exclusive block bases

// float atomic max via signed-max (>=0) / unsigned-min (<0); init must be -inf
__device__ __forceinline__ void atomicMaxFloat(float* addr, float val) {
    if (val >= 0.0f) atomicMax((int*)addr, __float_as_int(val));
    else             atomicMin((unsigned int*)addr, __float_as_uint(val));
}

// ---------------------------------------------------------------------------
__global__ void k_init(float* __restrict__ f_out) {
    int idx = blockIdx.x * blockDim.x + threadIdx.x;
    if (idx < N_NODES) g_cnt[idx] = 0;
    else if (idx < N_NODES + N_GRAPHS * D) f_out[idx - N_NODES] = -CUDART_INF_F;
    if (idx == 0) g_off[N_NODES] = N_EDGES;
}

// histogram of dst, 4 edges per thread
__global__ void k_hist(const int4* __restrict__ dst4) {
    int i = blockIdx.x * blockDim.x + threadIdx.x;
    if (i >= N_EDGES / 4) return;
    int4 d = __ldg(&dst4[i]);
    atomicAdd(&g_cnt[d.x], 1);
    atomicAdd(&g_cnt[d.y], 1);
    atomicAdd(&g_cnt[d.z], 1);
    atomicAdd(&g_cnt[d.w], 1);
}

// phase A: coalesced per-block exclusive scan (1024 elems/block)
__global__ void __launch_bounds__(1024) k_scanA() {
    __shared__ int wsum[32];
    int t = threadIdx.x, lane = t & 31, wid = t >> 5;
    int i = blockIdx.x * 1024 + t;
    int c = (i < N_NODES) ? g_cnt[i] : 0;
    int v = c;
#pragma unroll
    for (int o = 1; o < 32; o <<= 1) {
        int u = __shfl_up_sync(0xffffffffu, v, o);
        if (lane >= o) v += u;
    }
    if (lane == 31) wsum[wid] = v;
    __syncthreads();
    if (wid == 0) {
        int w = wsum[lane];
#pragma unroll
        for (int o = 1; o < 32; o <<= 1) {
            int u = __shfl_up_sync(0xffffffffu, w, o);
            if (lane >= o) w += u;
        }
        wsum[lane] = w;    // inclusive warp totals
    }
    __syncthreads();
    int base = wid ? wsum[wid - 1] : 0;
    if (i < N_NODES) {
        g_off[i] = base + v - c;   // block-local exclusive prefix
        g_deg[i] = (float)c;
    }
    if (t == 1023) g_bsum[blockIdx.x] = wsum[31];
}

// phase B: single small block scans the 98 block sums
__global__ void k_scanB() {
    __shared__ int s[128];
    int t = threadIdx.x;
    int v = (t < NBLK) ? g_bsum[t] : 0;
    s[t] = v;
    __syncthreads();
    for (int o = 1; o < 128; o <<= 1) {
        int u = (t >= o) ? s[t - o] : 0;
        __syncthreads();
        s[t] += u;
        __syncthreads();
    }
    if (t < NBLK) g_bbase[t] = s[t] - v;
}

// phase C: add block bases back, init cursors (coalesced)
__global__ void __launch_bounds__(1024) k_scanC() {
    int i = blockIdx.x * 1024 + threadIdx.x;
    if (i < N_NODES) {
        int o = g_off[i] + g_bbase[blockIdx.x];
        g_off[i] = o;
        g_cur[i] = o;
    }
}

// scatter src ids into dst-grouped order, 4 edges per thread
__global__ void k_scatter(const int4* __restrict__ src4, const int4* __restrict__ dst4) {
    int i = blockIdx.x * blockDim.x + threadIdx.x;
    if (i >= N_EDGES / 4) return;
    int4 d = __ldg(&dst4[i]);
    int4 s = __ldg(&src4[i]);
    g_esrc[atomicAdd(&g_cur[d.x], 1)] = s.x;
    g_esrc[atomicAdd(&g_cur[d.y], 1)] = s.y;
    g_esrc[atomicAdd(&g_cur[d.z], 1)] = s.z;
    g_esrc[atomicAdd(&g_cur[d.w], 1)] = s.w;
}

// ---------------------------------------------------------------------------
// CSR aggregation: one warp per dst node, half-warp per edge, float4 loads.
// 4 independent accumulators for MLP; cross-half combine via shfl_xor(16).
// ---------------------------------------------------------------------------
__global__ void __launch_bounds__(256) k_agg(const float4* __restrict__ feat4) {
    int lane = threadIdx.x & 31;
    int node = (blockIdx.x * blockDim.x + threadIdx.x) >> 5;
    if (node >= N_NODES) return;
    int start = g_off[node];
    int end   = g_off[node + 1];
    int half = lane >> 4;          // 0 or 1: which edge of a pair
    int q    = lane & 15;          // float4 chunk within row

    float4 a0 = make_float4(0.f, 0.f, 0.f, 0.f);
    float4 a1 = a0, a2 = a0, a3 = a0;

    int n8 = (end - start) >> 3;   // 8 edges (4 per half) per main iter
    int p = start + half;
    for (int it = 0; it < n8; it++, p += 8) {
        int s0 = __ldg(&g_esrc[p]);
        int s1 = __ldg(&g_esrc[p + 2]);
        int s2 = __ldg(&g_esrc[p + 4]);
        int s3 = __ldg(&g_esrc[p + 6]);
        float4 f0 = __ldg(&feat4[s0 * 16 + q]);
        float4 f1 = __ldg(&feat4[s1 * 16 + q]);
        float4 f2 = __ldg(&feat4[s2 * 16 + q]);
        float4 f3 = __ldg(&feat4[s3 * 16 + q]);
        a0.x += f0.x; a0.y += f0.y; a0.z += f0.z; a0.w += f0.w;
        a1.x += f1.x; a1.y += f1.y; a1.z += f1.z; a1.w += f1.w;
        a2.x += f2.x; a2.y += f2.y; a2.z += f2.z; a2.w += f2.w;
        a3.x += f3.x; a3.y += f3.y; a3.z += f3.z; a3.w += f3.w;
    }
    for (; p < end; p += 2) {
        float4 f = __ldg(&feat4[__ldg(&g_esrc[p]) * 16 + q]);
        a0.x += f.x; a0.y += f.y; a0.z += f.z; a0.w += f.w;
    }
    a0.x += a1.x + a2.x + a3.x;
    a0.y += a1.y + a2.y + a3.y;
    a0.z += a1.z + a2.z + a3.z;
    a0.w += a1.w + a2.w + a3.w;
    // combine the two half-warps
    a0.x += __shfl_xor_sync(0xffffffffu, a0.x, 16);
    a0.y += __shfl_xor_sync(0xffffffffu, a0.y, 16);
    a0.z += __shfl_xor_sync(0xffffffffu, a0.z, 16);
    a0.w += __shfl_xor_sync(0xffffffffu, a0.w, 16);
    if (half == 0) {
        reinterpret_cast<float4*>(g_agg)[node * 16 + q] = a0;
    }
}

// ---------------------------------------------------------------------------
// Node transform as block-tiled GEMM with XOR-swizzled staging:
//   out[128-node tile][64] = [x | agg/deg] (128x128) @ [Wself; Wneigh] (128x64)
// ---------------------------------------------------------------------------
#define TN 128
#define PITCH 132

template <bool RELU, bool POOL>
__global__ void __launch_bounds__(256)
k_gemm(const float* __restrict__ in,
       const float* __restrict__ Wself,
       const float* __restrict__ Wneigh,
       float* __restrict__ out,
       const int* __restrict__ graph_ids,
       float* __restrict__ fpool) {
    extern __shared__ float smem[];
    float* sIn = smem;                 // [128 k][PITCH cols (swizzled node idx)]
    float* sW  = smem + 128 * PITCH;   // [128 k][64 cols]

    int tid   = threadIdx.x;
    int node0 = blockIdx.x * TN;

    // load W tile: rows 0-63 = Wself, 64-127 = Wneigh
    for (int idx = tid; idx < 128 * 16; idx += 256) {
        int k  = idx >> 4;
        int c4 = (idx & 15) << 2;
        const float* wsrc = (k < 64) ? &Wself[k * D + c4] : &Wneigh[(k - 64) * D + c4];
        *(float4*)&sW[k * D + c4] = *(const float4*)wsrc;
    }

    // load input tile transposed with XOR-4 column swizzle
    for (int idx = tid; idx < TN * 32; idx += 256) {
        int n = idx >> 5;          // local node
        int c = idx & 31;          // float4 chunk: 0-15 => x, 16-31 => agg
        int node = node0 + n;
        int k = c << 2;            // both halves land at k = 4*(c&15)... see below
        float4 v = make_float4(0.f, 0.f, 0.f, 0.f);
        if (node < N_NODES) {
            if (c < 16) {
                v = *(const float4*)&in[node * D + k];
            } else {
                v = *(const float4*)&g_agg[node * D + (k - 64)];
                float inv = 1.0f / fmaxf(g_deg[node], 1.0f);
                v.x *= inv; v.y *= inv; v.z *= inv; v.w *= inv;
            }
        }
        int nc = n ^ ((c & 7) << 2);   // swizzled column (same for the 4 rows)
        sIn[(k + 0) * PITCH + nc] = v.x;
        sIn[(k + 1) * PITCH + nc] = v.y;
        sIn[(k + 2) * PITCH + nc] = v.z;
        sIn[(k + 3) * PITCH + nc] = v.w;
    }
    __syncthreads();

    int cx = tid & 15;     // col group: cols 4*cx .. 4*cx+3
    int nx = tid >> 4;     // node group: nodes 8*nx .. 8*nx+7

    float acc[8][4];
#pragma unroll
    for (int i = 0; i < 8; i++)
#pragma unroll
        for (int j = 0; j < 4; j++) acc[i][j] = 0.f;

#pragma unroll 4
    for (int k = 0; k < 128; k++) {
        int swz = ((k >> 2) & 7) << 2;
        float4 w  = *(float4*)&sW[k * D + 4 * cx];
        float4 p0 = *(float4*)&sIn[k * PITCH + ((8 * nx) ^ swz)];
        float4 p1 = *(float4*)&sIn[k * PITCH + ((8 * nx + 4) ^ swz)];
        float p[8] = {p0.x, p0.y, p0.z, p0.w, p1.x, p1.y, p1.z, p1.w};
#pragma unroll
        for (int i = 0; i < 8; i++) {
            acc[i][0] += p[i] * w.x;
            acc[i][1] += p[i] * w.y;
            acc[i][2] += p[i] * w.z;
            acc[i][3] += p[i] * w.w;
        }
    }

    // store + optional relu + optional fused per-graph max pool
    float4 runmax = make_float4(-CUDART_INF_F, -CUDART_INF_F, -CUDART_INF_F, -CUDART_INF_F);
    int curg = -1;
#pragma unroll
    for (int i = 0; i < 8; i++) {
        int node = node0 + 8 * nx + i;
        if (node >= N_NODES) break;
        float4 o = make_float4(acc[i][0], acc[i][1], acc[i][2], acc[i][3]);
        if (RELU) {
            o.x = fmaxf(o.x, 0.f); o.y = fmaxf(o.y, 0.f);
            o.z = fmaxf(o.z, 0.f); o.w = fmaxf(o.w, 0.f);
        }
        *(float4*)&out[node * D + 4 * cx] = o;
        if (POOL) {
            int g = __ldg(&graph_ids[node]);
            if (g != curg) {
                if (curg >= 0) {
                    atomicMaxFloat(&fpool[curg * D + 4 * cx + 0], runmax.x);
                    atomicMaxFloat(&fpool[curg * D + 4 * cx + 1], runmax.y);
                    atomicMaxFloat(&fpool[curg * D + 4 * cx + 2], runmax.z);
                    atomicMaxFloat(&fpool[curg * D + 4 * cx + 3], runmax.w);
                }
                curg = g;
                runmax = make_float4(-CUDART_INF_F, -CUDART_INF_F, -CUDART_INF_F, -CUDART_INF_F);
            }
            runmax.x = fmaxf(runmax.x, o.x);
            runmax.y = fmaxf(runmax.y, o.y);
            runmax.z = fmaxf(runmax.z, o.z);
            runmax.w = fmaxf(runmax.w, o.w);
        }
    }
    if (POOL && curg >= 0) {
        atomicMaxFloat(&fpool[curg * D + 4 * cx + 0], runmax.x);
        atomicMaxFloat(&fpool[curg * D + 4 * cx + 1], runmax.y);
        atomicMaxFloat(&fpool[curg * D + 4 * cx + 2], runmax.z);
        atomicMaxFloat(&fpool[curg * D + 4 * cx + 3], runmax.w);
    }
}

// ---------------------------------------------------------------------------
extern "C" void kernel_launch(void* const* d_in, const int* in_sizes, int n_in,
                              void* d_out, int out_size) {
    const float* x   = (const float*)d_in[0];
    const int*   src = (const int*)  d_in[1];
    const int*   dst = (const int*)  d_in[2];
    const int*   gid = (const int*)  d_in[3];
    const float* W0s = (const float*)d_in[4];
    const float* W0n = (const float*)d_in[5];
    const float* W1s = (const float*)d_in[6];
    const float* W1n = (const float*)d_in[7];

    float* out = (float*)d_out;
    float* f   = out;                   // [64, 64] pooled
    float* e   = out + N_GRAPHS * D;    // [100000, 64]

    void* hptr = nullptr;
    cudaGetSymbolAddress(&hptr, g_h);
    float* h = (float*)hptr;

    static bool attr_done = false;
    const int gemm_smem = (128 * PITCH + 128 * D) * (int)sizeof(float);
    if (!attr_done) {
        cudaFuncSetAttribute(k_gemm<true, false>,
                             cudaFuncAttributeMaxDynamicSharedMemorySize, gemm_smem);
        cudaFuncSetAttribute(k_gemm<false, true>,
                             cudaFuncAttributeMaxDynamicSharedMemorySize, gemm_smem);
        attr_done = true;
    }

    const int E4B = (N_EDGES / 4 + 255) / 256;

    k_init<<<(N_NODES + N_GRAPHS * D + 255) / 256, 256>>>(f);
    k_hist<<<E4B, 256>>>((const int4*)dst);
    k_scanA<<<NBLK, 1024>>>();
    k_scanB<<<1, 128>>>();
    k_scanC<<<NBLK, 1024>>>();
    k_scatter<<<E4B, 256>>>((const int4*)src, (const int4*)dst);

    const int AGG_B = (N_NODES * 32 + 255) / 256;
    const int GEMM_B = (N_NODES + TN - 1) / TN;

    // Layer 0
    k_agg<<<AGG_B, 256>>>((const float4*)x);
    k_gemm<true, false><<<GEMM_B, 256, gemm_smem>>>(x, W0s, W0n, h, gid, f);

    // Layer 1 + fused pool
    k_agg<<<AGG_B, 256>>>((const float4*)h);
    k_gemm<false, true><<<GEMM_B, 256, gemm_smem>>>(h, W1s, W1n, e, gid, f);
}

// round 4
// speedup vs baseline: 2.5972x; 1.0571x over previous
#include <cuda_runtime.h>
#include <math_constants.h>
#include <stdint.h>

#define N_NODES  100000
#define N_EDGES  1600000
#define D        64
#define N_GRAPHS 64
#define NBLK     ((N_NODES + 1023) / 1024)   // 98 scan blocks

// ---------------- device scratch (no allocations allowed) ------------------
__device__ float g_agg[N_NODES * D];      // neighbor sums (overwritten each layer)
__device__ float g_deg[N_NODES];
__device__ float g_h[N_NODES * D];        // layer-0 activations
__device__ int   g_cnt[N_NODES];          // histogram
__device__ int   g_off[N_NODES + 1];      // CSR offsets
__device__ int   g_esrc[N_EDGES];         // src ids grouped by dst
__device__ int   g_rank[N_EDGES];         // per-edge rank within its dst
__device__ int   g_bsum[NBLK];            // per-block scan sums
__device__ int   g_bbase[NBLK];           // exclusive block bases

// float atomic max via signed-max (>=0) / unsigned-min (<0); init must be -inf
__device__ __forceinline__ void atomicMaxFloat(float* addr, float val) {
    if (val >= 0.0f) atomicMax((int*)addr, __float_as_int(val));
    else             atomicMin((unsigned int*)addr, __float_as_uint(val));
}

// ---------------------------------------------------------------------------
__global__ void k_init(float* __restrict__ f_out) {
    int idx = blockIdx.x * blockDim.x + threadIdx.x;
    if (idx < N_NODES) g_cnt[idx] = 0;
    else if (idx < N_NODES + N_GRAPHS * D) f_out[idx - N_NODES] = -CUDART_INF_F;
    if (idx == 0) g_off[N_NODES] = N_EDGES;
}

// histogram of dst + per-edge rank capture, 4 edges per thread
__global__ void k_hist(const int4* __restrict__ dst4, int4* __restrict__ rank4) {
    int i = blockIdx.x * blockDim.x + threadIdx.x;
    if (i >= N_EDGES / 4) return;
    int4 d = __ldg(&dst4[i]);
    int4 r;
    r.x = atomicAdd(&g_cnt[d.x], 1);
    r.y = atomicAdd(&g_cnt[d.y], 1);
    r.z = atomicAdd(&g_cnt[d.z], 1);
    r.w = atomicAdd(&g_cnt[d.w], 1);
    rank4[i] = r;
}

// phase A: coalesced per-block exclusive scan (1024 elems/block)
__global__ void __launch_bounds__(1024) k_scanA() {
    __shared__ int wsum[32];
    int t = threadIdx.x, lane = t & 31, wid = t >> 5;
    int i = blockIdx.x * 1024 + t;
    int c = (i < N_NODES) ? g_cnt[i] : 0;
    int v = c;
#pragma unroll
    for (int o = 1; o < 32; o <<= 1) {
        int u = __shfl_up_sync(0xffffffffu, v, o);
        if (lane >= o) v += u;
    }
    if (lane == 31) wsum[wid] = v;
    __syncthreads();
    if (wid == 0) {
        int w = wsum[lane];
#pragma unroll
        for (int o = 1; o < 32; o <<= 1) {
            int u = __shfl_up_sync(0xffffffffu, w, o);
            if (lane >= o) w += u;
        }
        wsum[lane] = w;
    }
    __syncthreads();
    int base = wid ? wsum[wid - 1] : 0;
    if (i < N_NODES) {
        g_off[i] = base + v - c;
        g_deg[i] = (float)c;
    }
    if (t == 1023) g_bsum[blockIdx.x] = wsum[31];
}

// phase B: single small block scans the 98 block sums
__global__ void k_scanB() {
    __shared__ int s[128];
    int t = threadIdx.x;
    int v = (t < NBLK) ? g_bsum[t] : 0;
    s[t] = v;
    __syncthreads();
    for (int o = 1; o < 128; o <<= 1) {
        int u = (t >= o) ? s[t - o] : 0;
        __syncthreads();
        s[t] += u;
        __syncthreads();
    }
    if (t < NBLK) g_bbase[t] = s[t] - v;
}

// phase C: add block bases back (coalesced)
__global__ void __launch_bounds__(1024) k_scanC() {
    int i = blockIdx.x * 1024 + threadIdx.x;
    if (i < N_NODES) g_off[i] += g_bbase[blockIdx.x];
}

// scatter src ids into dst-grouped order using precomputed ranks (no atomics)
__global__ void k_scatter(const int4* __restrict__ src4, const int4* __restrict__ dst4,
                          const int4* __restrict__ rank4) {
    int i = blockIdx.x * blockDim.x + threadIdx.x;
    if (i >= N_EDGES / 4) return;
    int4 d = __ldg(&dst4[i]);
    int4 s = __ldg(&src4[i]);
    int4 r = __ldg(&rank4[i]);
    g_esrc[__ldg(&g_off[d.x]) + r.x] = s.x;
    g_esrc[__ldg(&g_off[d.y]) + r.y] = s.y;
    g_esrc[__ldg(&g_off[d.z]) + r.z] = s.z;
    g_esrc[__ldg(&g_off[d.w]) + r.w] = s.w;
}

// ---------------------------------------------------------------------------
// CSR aggregation: one warp per dst node, half-warp per edge, float4 loads.
// ---------------------------------------------------------------------------
__global__ void __launch_bounds__(256) k_agg(const float4* __restrict__ feat4) {
    int lane = threadIdx.x & 31;
    int node = (blockIdx.x * blockDim.x + threadIdx.x) >> 5;
    if (node >= N_NODES) return;
    int start = g_off[node];
    int end   = g_off[node + 1];
    int half = lane >> 4;
    int q    = lane & 15;

    float4 a0 = make_float4(0.f, 0.f, 0.f, 0.f);
    float4 a1 = a0, a2 = a0, a3 = a0;

    int n8 = (end - start) >> 3;
    int p = start + half;
    for (int it = 0; it < n8; it++, p += 8) {
        int s0 = __ldg(&g_esrc[p]);
        int s1 = __ldg(&g_esrc[p + 2]);
        int s2 = __ldg(&g_esrc[p + 4]);
        int s3 = __ldg(&g_esrc[p + 6]);
        float4 f0 = __ldg(&feat4[s0 * 16 + q]);
        float4 f1 = __ldg(&feat4[s1 * 16 + q]);
        float4 f2 = __ldg(&feat4[s2 * 16 + q]);
        float4 f3 = __ldg(&feat4[s3 * 16 + q]);
        a0.x += f0.x; a0.y += f0.y; a0.z += f0.z; a0.w += f0.w;
        a1.x += f1.x; a1.y += f1.y; a1.z += f1.z; a1.w += f1.w;
        a2.x += f2.x; a2.y += f2.y; a2.z += f2.z; a2.w += f2.w;
        a3.x += f3.x; a3.y += f3.y; a3.z += f3.z; a3.w += f3.w;
    }
    for (; p < end; p += 2) {
        float4 f = __ldg(&feat4[__ldg(&g_esrc[p]) * 16 + q]);
        a0.x += f.x; a0.y += f.y; a0.z += f.z; a0.w += f.w;
    }
    a0.x += a1.x + a2.x + a3.x;
    a0.y += a1.y + a2.y + a3.y;
    a0.z += a1.z + a2.z + a3.z;
    a0.w += a1.w + a2.w + a3.w;
    a0.x += __shfl_xor_sync(0xffffffffu, a0.x, 16);
    a0.y += __shfl_xor_sync(0xffffffffu, a0.y, 16);
    a0.z += __shfl_xor_sync(0xffffffffu, a0.z, 16);
    a0.w += __shfl_xor_sync(0xffffffffu, a0.w, 16);
    if (half == 0) {
        reinterpret_cast<float4*>(g_agg)[node * 16 + q] = a0;
    }
}

// ---------------------------------------------------------------------------
// 3xTF32 tensor-core GEMM:
//   out[128-node tile][64] = [x | agg/deg] (128x128) @ [Wself; Wneigh] (128x64)
// A split a=ah+al (tf32), W split w=wh+wl; C = ah*wh + al*wh + ah*wl (fp32 acc).
// mma.sync.m16n8k8 tf32. Warp = one 16-row m-tile; 8 n-tiles of 8 cols.
// ---------------------------------------------------------------------------
#define TN 128
#define A_PITCH 132
#define W_PITCH 72

__device__ __forceinline__ void split_tf32(float x, uint32_t& hi, uint32_t& lo) {
    asm("cvt.rna.tf32.f32 %0, %1;" : "=r"(hi) : "f"(x));
    float l = x - __uint_as_float(hi);
    asm("cvt.rna.tf32.f32 %0, %1;" : "=r"(lo) : "f"(l));
}

__device__ __forceinline__ void mma_tf32(float* d, const uint32_t* a,
                                         uint32_t b0, uint32_t b1) {
    asm volatile(
        "mma.sync.aligned.m16n8k8.row.col.f32.tf32.tf32.f32 "
        "{%0,%1,%2,%3}, {%4,%5,%6,%7}, {%8,%9}, {%0,%1,%2,%3};"
        : "+f"(d[0]), "+f"(d[1]), "+f"(d[2]), "+f"(d[3])
        : "r"(a[0]), "r"(a[1]), "r"(a[2]), "r"(a[3]), "r"(b0), "r"(b1));
}

template <bool RELU>
__global__ void __launch_bounds__(256, 2)
k_gemm(const float* __restrict__ in,
       const float* __restrict__ Wself,
       const float* __restrict__ Wneigh,
       float* __restrict__ out) {
    extern __shared__ float smem[];
    float* sIn = smem;                       // [128 nodes][A_PITCH] fp32
    float* sW  = smem + TN * A_PITCH;        // [128 k][W_PITCH] fp32

    int tid   = threadIdx.x;
    int node0 = blockIdx.x * TN;

    // stage W: [128 k][72 pitch]; rows 0-63 = Wself, 64-127 = Wneigh
    for (int idx = tid; idx < 128 * 16; idx += 256) {
        int k  = idx >> 4;
        int n4 = (idx & 15) << 2;
        const float* wsrc = (k < 64) ? &Wself[k * D + n4] : &Wneigh[(k - 64) * D + n4];
        *(float4*)&sW[k * W_PITCH + n4] = *(const float4*)wsrc;
    }

    // stage input tile node-major: k<64 from x, k>=64 from agg/deg
    for (int idx = tid; idx < TN * 32; idx += 256) {
        int n  = idx >> 5;
        int c4 = idx & 31;            // k chunk: k0 = 4*c4
        int node = node0 + n;
        int k0 = c4 << 2;
        float4 v = make_float4(0.f, 0.f, 0.f, 0.f);
        if (node < N_NODES) {
            if (c4 < 16) {
                v = *(const float4*)&in[node * D + k0];
            } else {
                v = *(const float4*)&g_agg[node * D + (k0 - 64)];
                float inv = 1.0f / fmaxf(g_deg[node], 1.0f);
                v.x *= inv; v.y *= inv; v.z *= inv; v.w *= inv;
            }
        }
        *(float4*)&sIn[n * A_PITCH + k0] = v;
    }
    __syncthreads();

    int lane = tid & 31;
    int mt   = tid >> 5;          // warp = m-tile (16 nodes)
    int gq   = lane >> 2;         // groupID
    int cq   = lane & 3;          // thread-in-group

    float acc[8][4];
#pragma unroll
    for (int i = 0; i < 8; i++)
#pragma unroll
        for (int j = 0; j < 4; j++) acc[i][j] = 0.f;

    const float* aBase = sIn + (mt * 16 + gq) * A_PITCH + cq;
    const float* bBase = sW + cq * W_PITCH + gq;

#pragma unroll 1
    for (int ks = 0; ks < 16; ks++) {
        float a0 = aBase[ks * 8];
        float a1 = aBase[ks * 8 + 8 * A_PITCH];
        float a2 = aBase[ks * 8 + 4];
        float a3 = aBase[ks * 8 + 8 * A_PITCH + 4];
        uint32_t ah[4], al[4];
        split_tf32(a0, ah[0], al[0]);
        split_tf32(a1, ah[1], al[1]);
        split_tf32(a2, ah[2], al[2]);
        split_tf32(a3, ah[3], al[3]);
        const float* bk = bBase + ks * 8 * W_PITCH;
#pragma unroll
        for (int nt = 0; nt < 8; nt++) {
            float b0 = bk[nt * 8];
            float b1 = bk[4 * W_PITCH + nt * 8];
            uint32_t bh0, bl0, bh1, bl1;
            split_tf32(b0, bh0, bl0);
            split_tf32(b1, bh1, bl1);
            mma_tf32(acc[nt], ah, bh0, bh1);
            mma_tf32(acc[nt], al, bh0, bh1);
            mma_tf32(acc[nt], ah, bl0, bl1);
        }
    }

    // epilogue: c0,c1 -> (row, 2cq), (row, 2cq+1); c2,c3 -> row+8
    int nodeA = node0 + mt * 16 + gq;
    int nodeB = nodeA + 8;
#pragma unroll
    for (int nt = 0; nt < 8; nt++) {
        int col = nt * 8 + 2 * cq;
        float2 oA = make_float2(acc[nt][0], acc[nt][1]);
        float2 oB = make_float2(acc[nt][2], acc[nt][3]);
        if (RELU) {
            oA.x = fmaxf(oA.x, 0.f); oA.y = fmaxf(oA.y, 0.f);
            oB.x = fmaxf(oB.x, 0.f); oB.y = fmaxf(oB.y, 0.f);
        }
        if (nodeA < N_NODES) *(float2*)&out[nodeA * D + col] = oA;
        if (nodeB < N_NODES) *(float2*)&out[nodeB * D + col] = oB;
    }
}

// ---------------------------------------------------------------------------
// Per-graph max pool over e: 128 blocks scan contiguous node ranges.
// ---------------------------------------------------------------------------
#define POOL_CHUNK 782
__global__ void __launch_bounds__(256) k_pool(const float4* __restrict__ e4,
                                              const int* __restrict__ gid,
                                              float* __restrict__ fpool) {
    int q  = threadIdx.x & 15;
    int rl = threadIdx.x >> 4;
    int row0   = blockIdx.x * POOL_CHUNK;
    int rowEnd = min(row0 + POOL_CHUNK, N_NODES);
    float4 m = make_float4(-CUDART_INF_F, -CUDART_INF_F, -CUDART_INF_F, -CUDART_INF_F);
    int curg = -1;
    for (int r = row0 + rl; r < rowEnd; r += 16) {
        int g = __ldg(&gid[r]);
        float4 v = __ldg(&e4[r * 16 + q]);
        if (g != curg) {
            if (curg >= 0) {
                atomicMaxFloat(&fpool[curg * D + 4 * q + 0], m.x);
                atomicMaxFloat(&fpool[curg * D + 4 * q + 1], m.y);
                atomicMaxFloat(&fpool[curg * D + 4 * q + 2], m.z);
                atomicMaxFloat(&fpool[curg * D + 4 * q + 3], m.w);
            }
            curg = g;
            m = make_float4(-CUDART_INF_F, -CUDART_INF_F, -CUDART_INF_F, -CUDART_INF_F);
        }
        m.x = fmaxf(m.x, v.x); m.y = fmaxf(m.y, v.y);
        m.z = fmaxf(m.z, v.z); m.w = fmaxf(m.w, v.w);
    }
    if (curg >= 0) {
        atomicMaxFloat(&fpool[curg * D + 4 * q + 0], m.x);
        atomicMaxFloat(&fpool[curg * D + 4 * q + 1], m.y);
        atomicMaxFloat(&fpool[curg * D + 4 * q + 2], m.z);
        atomicMaxFloat(&fpool[curg * D + 4 * q + 3], m.w);
    }
}

// ---------------------------------------------------------------------------
extern "C" void kernel_launch(void* const* d_in, const int* in_sizes, int n_in,
                              void* d_out, int out_size) {
    const float* x   = (const float*)d_in[0];
    const int*   src = (const int*)  d_in[1];
    const int*   dst = (const int*)  d_in[2];
    const int*   gid = (const int*)  d_in[3];
    const float* W0s = (const float*)d_in[4];
    const float* W0n = (const float*)d_in[5];
    const float* W1s = (const float*)d_in[6];
    const float* W1n = (const float*)d_in[7];

    float* out = (float*)d_out;
    float* f   = out;                   // [64, 64] pooled
    float* e   = out + N_GRAPHS * D;    // [100000, 64]

    void* hptr = nullptr;
    cudaGetSymbolAddress(&hptr, g_h);
    float* h = (float*)hptr;
    void* rptr = nullptr;
    cudaGetSymbolAddress(&rptr, g_rank);
    int4* rank4 = (int4*)rptr;

    static bool attr_done = false;
    const int gemm_smem = (TN * A_PITCH + 128 * W_PITCH) * (int)sizeof(float);
    if (!attr_done) {
        cudaFuncSetAttribute(k_gemm<true>,
                             cudaFuncAttributeMaxDynamicSharedMemorySize, gemm_smem);
        cudaFuncSetAttribute(k_gemm<false>,
                             cudaFuncAttributeMaxDynamicSharedMemorySize, gemm_smem);
        attr_done = true;
    }

    const int E4B = (N_EDGES / 4 + 255) / 256;

    k_init<<<(N_NODES + N_GRAPHS * D + 255) / 256, 256>>>(f);
    k_hist<<<E4B, 256>>>((const int4*)dst, rank4);
    k_scanA<<<NBLK, 1024>>>();
    k_scanB<<<1, 128>>>();
    k_scanC<<<NBLK, 1024>>>();
    k_scatter<<<E4B, 256>>>((const int4*)src, (const int4*)dst, (const int4*)rank4);

    const int AGG_B = (N_NODES * 32 + 255) / 256;
    const int GEMM_B = (N_NODES + TN - 1) / TN;

    // Layer 0
    k_agg<<<AGG_B, 256>>>((const float4*)x);
    k_gemm<true><<<GEMM_B, 256, gemm_smem>>>(x, W0s, W0n, h);

    // Layer 1
    k_agg<<<AGG_B, 256>>>((const float4*)h);
    k_gemm<false><<<GEMM_B, 256, gemm_smem>>>(h, W1s, W1n, e);

    // Graph max-pool
    k_pool<<<(N_NODES + POOL_CHUNK - 1) / POOL_CHUNK, 256>>>((const float4*)e, gid, f);
}